// round 16
// baseline (speedup 1.0000x reference)
#include <cuda_runtime.h>
#include <cuda_bf16.h>
#include <math.h>
#include <stdint.h>

#define NN 4096
#define DD 256
#define HH 8
#define HDIM 32
#define ROWCAP 256
#define EPS 1e-5f
#define FFD 512

// ---------------- static scratch ----------------
__device__ int   g_cols[NN * ROWCAP];
__device__ float g_avals[NN * ROWCAP];
__device__ int   g_nnz[NN];
__device__ float g_Q[NN * DD];
__device__ float g_K[NN * DD];
__device__ float g_V[NN * DD];
__device__ float g_x1[NN * DD];
__device__ float g_bn1[NN * DD];
__device__ float g_x2[NN * DD];
__device__ float g_stats[1280];

// expanded 3xBF16 operand buffers (uint32 = bf16x2), 24 words per (chunk,row)
__device__ __align__(16) uint32_t g_hA  [NN * (DD / 16) * 24];
__device__ __align__(16) uint32_t g_attnA[NN * (DD / 16) * 24];
__device__ __align__(16) uint32_t g_bn1A[NN * (DD / 16) * 24];
__device__ __align__(16) uint32_t g_midA[NN * (FFD / 16) * 24];
__device__ __align__(16) uint32_t g_WqB [DD * (DD / 16) * 24];
__device__ __align__(16) uint32_t g_WkB [DD * (DD / 16) * 24];
__device__ __align__(16) uint32_t g_WvB [DD * (DD / 16) * 24];
__device__ __align__(16) uint32_t g_WoB [DD * (DD / 16) * 24];
__device__ __align__(16) uint32_t g_W1B [FFD * (DD / 16) * 24];
__device__ __align__(16) uint32_t g_W2B [DD * (FFD / 16) * 24];

// ================= helpers =================
__device__ __forceinline__ uint32_t smem_u32(const void* p) {
    uint32_t a;
    asm("{ .reg .u64 t; cvta.to.shared.u64 t, %1; cvt.u32.u64 %0, t; }" : "=r"(a) : "l"(p));
    return a;
}
__device__ __forceinline__ void ldm4(uint32_t addr, uint32_t& r0, uint32_t& r1,
                                     uint32_t& r2, uint32_t& r3) {
    asm volatile("ldmatrix.sync.aligned.m8n8.x4.shared.b16 {%0,%1,%2,%3}, [%4];"
                 : "=r"(r0), "=r"(r1), "=r"(r2), "=r"(r3) : "r"(addr));
}
__device__ __forceinline__ void mma16816(float* c, uint32_t a0, uint32_t a1,
                                         uint32_t a2, uint32_t a3,
                                         uint32_t b0, uint32_t b1) {
    asm volatile(
        "mma.sync.aligned.m16n8k16.row.col.f32.bf16.bf16.f32 "
        "{%0,%1,%2,%3}, {%4,%5,%6,%7}, {%8,%9}, {%0,%1,%2,%3};"
        : "+f"(c[0]), "+f"(c[1]), "+f"(c[2]), "+f"(c[3])
        : "r"(a0), "r"(a1), "r"(a2), "r"(a3), "r"(b0), "r"(b1));
}
#define CP16(dst, src) asm volatile("cp.async.cg.shared.global [%0], [%1], 16;" :: "r"(dst), "l"(src))
#define CPCOMMIT()     asm volatile("cp.async.commit_group;" ::: "memory")
#define CPWAIT2()      asm volatile("cp.async.wait_group 2;" ::: "memory")

__device__ __forceinline__ void splitf(float x, uint32_t& h, uint32_t& l) {
    __nv_bfloat16 hb = __float2bfloat16_rn(x);
    float hf = __bfloat162float(hb);
    __nv_bfloat16 lb = __float2bfloat16_rn(x - hf);
    h = (uint32_t)__bfloat16_as_ushort(hb);
    l = (uint32_t)__bfloat16_as_ushort(lb);
}
// A per float: [hi, lo, hi];  B per float: [hi, hi, lo]
__device__ __forceinline__ void packA(float a, float b, uint32_t* w) {
    uint32_t ha, la, hb, lb;
    splitf(a, ha, la); splitf(b, hb, lb);
    w[0] = ha | (la << 16); w[1] = ha | (hb << 16); w[2] = lb | (hb << 16);
}
__device__ __forceinline__ void packB(float a, float b, uint32_t* w) {
    uint32_t ha, la, hb, lb;
    splitf(a, ha, la); splitf(b, hb, lb);
    w[0] = ha | (ha << 16); w[1] = la | (hb << 16); w[2] = hb | (lb << 16);
}

// ================= merged prep: csr + expandA + expandB + zero stats =========
__global__ void __launch_bounds__(256) prep(
    const float* __restrict__ A, const float* __restrict__ h,
    const float* __restrict__ Wq, const float* __restrict__ Wk,
    const float* __restrict__ Wv, const float* __restrict__ Wo,
    const float* __restrict__ W1, const float* __restrict__ W2)
{
    __shared__ int cnt;
    int bid = blockIdx.x;
    if (bid < NN) {
        int row = bid;
        if (threadIdx.x == 0) cnt = 0;
        __syncthreads();
        const float4* Ar = (const float4*)(A + (size_t)row * NN);
        for (int c4 = threadIdx.x; c4 < NN / 4; c4 += 256) {
            float4 a4 = Ar[c4];
            float vals[4] = {a4.x, a4.y, a4.z, a4.w};
#pragma unroll
            for (int j = 0; j < 4; j++) {
                if (vals[j] != 0.0f) {
                    int p = atomicAdd(&cnt, 1);
                    if (p < ROWCAP) {
                        g_cols[row * ROWCAP + p] = c4 * 4 + j;
                        g_avals[row * ROWCAP + p] = vals[j];
                    }
                }
            }
        }
        __syncthreads();
        if (threadIdx.x == 0) g_nnz[row] = (cnt < ROWCAP) ? cnt : ROWCAP;
    } else if (bid < NN + 512) {
        int eb = bid - NN;
        if (eb < 5) g_stats[eb * 256 + threadIdx.x] = 0.0f;
        int idx = eb * 256 + threadIdx.x;
        const int hpr = DD / 8;
        int row = idx / hpr, wi = idx - row * hpr;
        int chunk = wi >> 1, half = wi & 1;
        const float4* s4 = (const float4*)&h[(size_t)row * DD + chunk * 16 + half * 8];
        float4 v0 = s4[0], v1 = s4[1];
        float f[8] = {v0.x, v0.y, v0.z, v0.w, v1.x, v1.y, v1.z, v1.w};
        uint32_t w[12];
#pragma unroll
        for (int p = 0; p < 4; p++) packA(f[2 * p], f[2 * p + 1], w + 3 * p);
        uint32_t* d = g_hA + ((size_t)chunk * NN + row) * 24 + half * 12;
        *(uint4*)(d + 0) = make_uint4(w[0], w[1], w[2], w[3]);
        *(uint4*)(d + 4) = make_uint4(w[4], w[5], w[6], w[7]);
        *(uint4*)(d + 8) = make_uint4(w[8], w[9], w[10], w[11]);
    } else {
        int eb = bid - NN - 512;
        int which = eb >> 6;
        int bx = eb & 63;
        const float* src; uint32_t* dst; int rows, K;
        switch (which) {
            case 0: src = Wq; dst = g_WqB; rows = DD;  K = DD;  break;
            case 1: src = Wk; dst = g_WkB; rows = DD;  K = DD;  break;
            case 2: src = Wv; dst = g_WvB; rows = DD;  K = DD;  break;
            case 3: src = Wo; dst = g_WoB; rows = DD;  K = DD;  break;
            case 4: src = W1; dst = g_W1B; rows = FFD; K = DD;  break;
            default: src = W2; dst = g_W2B; rows = DD; K = FFD; break;
        }
        int idx = bx * 256 + threadIdx.x;
        int hpr = K / 8;
        if (idx >= rows * hpr) return;
        int row = idx / hpr, wi = idx - row * hpr;
        int chunk = wi >> 1, half = wi & 1;
        const float4* s4 = (const float4*)&src[(size_t)row * K + chunk * 16 + half * 8];
        float4 v0 = s4[0], v1 = s4[1];
        float f[8] = {v0.x, v0.y, v0.z, v0.w, v1.x, v1.y, v1.z, v1.w};
        uint32_t w[12];
#pragma unroll
        for (int p = 0; p < 4; p++) packB(f[2 * p], f[2 * p + 1], w + 3 * p);
        uint32_t* d = dst + ((size_t)chunk * rows + row) * 24 + half * 12;
        *(uint4*)(d + 0) = make_uint4(w[0], w[1], w[2], w[3]);
        *(uint4*)(d + 4) = make_uint4(w[4], w[5], w[6], w[7]);
        *(uint4*)(d + 8) = make_uint4(w[8], w[9], w[10], w[11]);
    }
}

// ================= pipelined bf16 GEMM, 32x64 tile, 128 threads ==============
// 4 stages + wait_group 2, commit EVERY iter (race-free tail accounting).
// Warp tile 16x32 (2x2 warps). Stage = A 32x112 + B 64x112 = 10752 B.
#define BM 32
#define BN 64
#define STAGEB 10752
#define NSTG 4
#define GEMM_SMEM (NSTG * STAGEB)
#define NLINES ((BM + BN) * 6)    // 576 16B lines per stage
#define A_LINES (BM * 6)          // 192
#define B_OFF (BM * 112)          // 3584

__device__ __forceinline__ void gemm_ex_body(
    const char* __restrict__ Aex, const char* __restrict__ Bex,
    float* __restrict__ Y, int K, int Ncr,
    int mode, const float* __restrict__ res, float scale,
    float* __restrict__ vsums)
{
    extern __shared__ __align__(16) char sm[];
    uint32_t smb = smem_u32(sm);

    int tid = threadIdx.x;
    int lane = tid & 31;
    int wid = tid >> 5;          // 0..3
    int wm = wid >> 1;           // 0..1 -> m offset *16
    int wn = wid & 1;            // 0..1 -> n offset *32
    int m0 = blockIdx.y * BM;
    int n0 = blockIdx.x * BN;

    const size_t aChunk = (size_t)NN * 96;
    const size_t bChunk = (size_t)Ncr * 96;

    // per-thread load lines: up to 5 (576 lines / 128 threads)
    size_t srcOff[5];
    uint32_t dstOff[5];
    bool isA[5];
    int nl = 0;
#pragma unroll
    for (int i = 0; i < 5; i++) {
        int l = tid + i * 128;
        if (l < NLINES) {
            if (l < A_LINES) {
                int row = l / 6, part = l - row * 6;
                srcOff[nl] = (size_t)(m0 + row) * 96 + part * 16;
                dstOff[nl] = (uint32_t)(row * 112 + part * 16);
                isA[nl] = true;
            } else {
                int l2 = l - A_LINES;
                int row = l2 / 6, part = l2 - row * 6;
                srcOff[nl] = (size_t)(n0 + row) * 96 + part * 16;
                dstOff[nl] = (uint32_t)(B_OFF + row * 112 + part * 16);
                isA[nl] = false;
            }
            nl++;
        }
    }

    int nit = K / 16;

    // prologue: stages 0..2
#pragma unroll
    for (int s = 0; s < 3; s++) {
        uint32_t sb = smb + s * STAGEB;
        for (int i = 0; i < nl; i++) {
            const char* base = isA[i] ? (Aex + (size_t)s * aChunk)
                                      : (Bex + (size_t)s * bChunk);
            CP16(sb + dstOff[i], base + srcOff[i]);
        }
        CPCOMMIT();
    }

    int la = lane & 15;
    int kha = (lane >> 4) & 1;
    int rb = (lane & 7) + (((lane >> 4) & 1) << 3);
    int khb = (lane >> 3) & 1;
    uint32_t aRow = (uint32_t)((wm * 16 + la) * 112);
    uint32_t bRow[2];
#pragma unroll
    for (int nt = 0; nt < 2; nt++)
        bRow[nt] = (uint32_t)(B_OFF + (wn * 32 + nt * 16 + rb) * 112);

    float acc[4][4] = {};

    for (int it = 0; it < nit; it++) {
        CPWAIT2();
        __syncthreads();
        int nc3 = it + 3;
        if (nc3 < nit) {
            uint32_t sb = smb + (nc3 % NSTG) * STAGEB;
            for (int i = 0; i < nl; i++) {
                const char* base = isA[i] ? (Aex + (size_t)nc3 * aChunk)
                                          : (Bex + (size_t)nc3 * bChunk);
                CP16(sb + dstOff[i], base + srcOff[i]);
            }
        }
        CPCOMMIT();   // ALWAYS commit — exact wait_group accounting
        uint32_t base = smb + (it % NSTG) * STAGEB;
#pragma unroll
        for (int ks = 0; ks < 3; ks++) {
            uint32_t koff = (uint32_t)(2 * ks) * 16;
            uint32_t a[4], b[2][4];
            ldm4(base + aRow + koff + (uint32_t)kha * 16, a[0], a[1], a[2], a[3]);
#pragma unroll
            for (int nt = 0; nt < 2; nt++)
                ldm4(base + bRow[nt] + koff + (uint32_t)khb * 16,
                     b[nt][0], b[nt][1], b[nt][2], b[nt][3]);
#pragma unroll
            for (int nt = 0; nt < 2; nt++) {
                mma16816(acc[nt * 2 + 0], a[0], a[1], a[2], a[3], b[nt][0], b[nt][1]);
                mma16816(acc[nt * 2 + 1], a[0], a[1], a[2], a[3], b[nt][2], b[nt][3]);
            }
        }
    }

    // ---- epilogue
    int gid = lane >> 2, tig = lane & 3;
#pragma unroll
    for (int n8 = 0; n8 < 4; n8++) {
        int col = n0 + wn * 32 + n8 * 8 + 2 * tig;
        float s0 = 0.f, s1 = 0.f;
#pragma unroll
        for (int half = 0; half < 2; half++) {
            int m = m0 + wm * 16 + gid + half * 8;
            size_t rowoff = (size_t)m * Ncr;
            float v0 = acc[n8][half * 2 + 0];
            float v1 = acc[n8][half * 2 + 1];
            if (mode == 1) {
                int p0 = (col & 7) * HDIM + (col >> 3);
                int p1 = ((col + 1) & 7) * HDIM + ((col + 1) >> 3);
                Y[rowoff + p0] = v0 * scale;
                Y[rowoff + p1] = v1 * scale;
                s0 += v0; s1 += v1;
            } else if (mode == 2) {
                float r0 = fmaxf(v0, 0.f), r1 = fmaxf(v1, 0.f);
                uint32_t w[3];
                packA(r0, r1, w);
                size_t base2 = ((size_t)(col >> 4) * NN + m) * 24 + ((col & 15) >> 1) * 3;
                g_midA[base2 + 0] = w[0];
                g_midA[base2 + 1] = w[1];
                g_midA[base2 + 2] = w[2];
            } else if (mode == 3) {
                float2 r = *(const float2*)&res[rowoff + col];
                *(float2*)&Y[rowoff + col] = make_float2(v0 + r.x, v1 + r.y);
            } else {
                *(float2*)&Y[rowoff + col] = make_float2(v0, v1);
            }
        }
        if (mode == 1 && vsums != nullptr) {
#pragma unroll
            for (int off = 4; off < 32; off <<= 1) {
                s0 += __shfl_xor_sync(0xffffffffu, s0, off);
                s1 += __shfl_xor_sync(0xffffffffu, s1, off);
            }
            if (gid == 0) {
                int p0 = (col & 7) * HDIM + (col >> 3);
                int p1 = ((col + 1) & 7) * HDIM + ((col + 1) >> 3);
                atomicAdd(&vsums[p0], s0);
                atomicAdd(&vsums[p1], s1);
            }
        }
    }
}

__global__ void __launch_bounds__(128) qkv_gemm_ex(const char* __restrict__ Aex,
                                                   float* __restrict__ stats) {
    int z = blockIdx.z;
    const char* Bex = (z == 0) ? (const char*)g_WqB : ((z == 1) ? (const char*)g_WkB : (const char*)g_WvB);
    float* Y = (z == 0) ? g_Q : ((z == 1) ? g_K : g_V);
    float scale = (z == 0) ? 0.0625f : 1.0f;
    gemm_ex_body(Aex, Bex, Y, DD, DD, 1, nullptr, scale,
                 (z == 2) ? stats : nullptr);
}

__global__ void __launch_bounds__(128) gemm_ex(
    const char* __restrict__ Aex, const char* __restrict__ Bex,
    float* __restrict__ Y, int K, int Ncr, int mode, const float* __restrict__ res)
{
    gemm_ex_body(Aex, Bex, Y, K, Ncr, mode, res, 1.0f, nullptr);
}

// ================= attention (R11-proven) ==================
__global__ void __launch_bounds__(256) attn_sparse() {
    __shared__ float s_part[8][DD];
    __shared__ float s_zp[8][HH];
    __shared__ float sm_attn[DD];
    __shared__ int   s_cols[ROWCAP];
    __shared__ float s_av[ROWCAP];
    int n = blockIdx.x;
    int tid = threadIdx.x;
    int w = tid >> 5;
    int lane = tid & 31;
    int d0 = lane * 8;

    int nnz = g_nnz[n];
    if (tid < nnz) {
        s_cols[tid] = g_cols[(size_t)n * ROWCAP + tid];
        s_av[tid]   = g_avals[(size_t)n * ROWCAP + tid];
    }
    float4 q0 = *(const float4*)&g_Q[(size_t)n * DD + d0];
    float4 q1 = *(const float4*)&g_Q[(size_t)n * DD + d0 + 4];
    __syncthreads();

    float a0 = 0.f, a1 = 0.f, a2 = 0.f, a3 = 0.f;
    float a4 = 0.f, a5 = 0.f, a6 = 0.f, a7 = 0.f;
    float zloc = 0.0f;

    int i = w;
    for (; i + 8 < nnz; i += 16) {
        int mA = s_cols[i],   mB = s_cols[i + 8];
        float avA = s_av[i],  avB = s_av[i + 8];
        const float* KrA = &g_K[(size_t)mA * DD + d0];
        const float* VrA = &g_V[(size_t)mA * DD + d0];
        const float* KrB = &g_K[(size_t)mB * DD + d0];
        const float* VrB = &g_V[(size_t)mB * DD + d0];
        float4 kA0 = *(const float4*)&KrA[0];
        float4 kA1 = *(const float4*)&KrA[4];
        float4 kB0 = *(const float4*)&KrB[0];
        float4 kB1 = *(const float4*)&KrB[4];
        float4 vA0 = *(const float4*)&VrA[0];
        float4 vA1 = *(const float4*)&VrA[4];
        float4 vB0 = *(const float4*)&VrB[0];
        float4 vB1 = *(const float4*)&VrB[4];
        float sA = q0.x * kA0.x + q0.y * kA0.y + q0.z * kA0.z + q0.w * kA0.w
                 + q1.x * kA1.x + q1.y * kA1.y + q1.z * kA1.z + q1.w * kA1.w;
        float sB = q0.x * kB0.x + q0.y * kB0.y + q0.z * kB0.z + q0.w * kB0.w
                 + q1.x * kB1.x + q1.y * kB1.y + q1.z * kB1.z + q1.w * kB1.w;
        sA += __shfl_xor_sync(0xffffffffu, sA, 1);
        sB += __shfl_xor_sync(0xffffffffu, sB, 1);
        sA += __shfl_xor_sync(0xffffffffu, sA, 2);
        sB += __shfl_xor_sync(0xffffffffu, sB, 2);
        float eA = __expf(avA * sA);
        float eB = __expf(avB * sB);
        float emA = eA - 1.0f, emB = eB - 1.0f;
        a0 += emA * vA0.x + emB * vB0.x;
        a1 += emA * vA0.y + emB * vB0.y;
        a2 += emA * vA0.z + emB * vB0.z;
        a3 += emA * vA0.w + emB * vB0.w;
        a4 += emA * vA1.x + emB * vB1.x;
        a5 += emA * vA1.y + emB * vB1.y;
        a6 += emA * vA1.z + emB * vB1.z;
        a7 += emA * vA1.w + emB * vB1.w;
        if ((lane & 3) == 0) zloc += eA + eB;
    }
    if (i < nnz) {
        int m = s_cols[i];
        float av_i = s_av[i];
        const float* Kr = &g_K[(size_t)m * DD + d0];
        const float* Vr = &g_V[(size_t)m * DD + d0];
        float4 k0 = *(const float4*)&Kr[0];
        float4 k1 = *(const float4*)&Kr[4];
        float4 v0 = *(const float4*)&Vr[0];
        float4 v1 = *(const float4*)&Vr[4];
        float s = q0.x * k0.x + q0.y * k0.y + q0.z * k0.z + q0.w * k0.w
                + q1.x * k1.x + q1.y * k1.y + q1.z * k1.z + q1.w * k1.w;
        s += __shfl_xor_sync(0xffffffffu, s, 1);
        s += __shfl_xor_sync(0xffffffffu, s, 2);
        float e = __expf(av_i * s);
        float em1 = e - 1.0f;
        a0 += em1 * v0.x; a1 += em1 * v0.y; a2 += em1 * v0.z; a3 += em1 * v0.w;
        a4 += em1 * v1.x; a5 += em1 * v1.y; a6 += em1 * v1.z; a7 += em1 * v1.w;
        if ((lane & 3) == 0) zloc += e;
    }

    *(float4*)&s_part[w][d0]     = make_float4(a0, a1, a2, a3);
    *(float4*)&s_part[w][d0 + 4] = make_float4(a4, a5, a6, a7);
    if ((lane & 3) == 0) s_zp[w][lane >> 2] = zloc;
    __syncthreads();

    {
        int c = tid;
        int p = (c & 7) * HDIM + (c >> 3);
        float acc = g_stats[p];
        float z = (float)(NN - nnz);
#pragma unroll
        for (int ww = 0; ww < 8; ww++) {
            acc += s_part[ww][p];
            z += s_zp[ww][c & 7];
        }
        sm_attn[c] = acc / z;
    }
    __syncthreads();
    if (tid < 128) {
        int c0 = 2 * tid;
        float v0 = sm_attn[c0], v1 = sm_attn[c0 + 1];
        uint32_t ww[3];
        packA(v0, v1, ww);
        size_t b = ((size_t)(c0 >> 4) * NN + n) * 24 + ((c0 & 15) >> 1) * 3;
        g_attnA[b + 0] = ww[0];
        g_attnA[b + 1] = ww[1];
        g_attnA[b + 2] = ww[2];
    }
}

// ================= batchnorm (R6-proven) =================
__global__ void __launch_bounds__(256) bn_stats(
    const float* __restrict__ X, float* __restrict__ sums, float* __restrict__ sqs)
{
    int c4 = threadIdx.x & 63;
    int rs = threadIdx.x >> 6;
    int r0 = blockIdx.x * 16;
    float4 s = make_float4(0.f, 0.f, 0.f, 0.f);
    float4 q = make_float4(0.f, 0.f, 0.f, 0.f);
#pragma unroll
    for (int j = 0; j < 4; j++) {
        int r = r0 + rs * 4 + j;
        float4 v = *(const float4*)&X[(size_t)r * DD + c4 * 4];
        s.x += v.x; s.y += v.y; s.z += v.z; s.w += v.w;
        q.x += v.x * v.x; q.y += v.y * v.y; q.z += v.z * v.z; q.w += v.w * v.w;
    }
    __shared__ float4 rs_[4][64], rq_[4][64];
    rs_[rs][c4] = s; rq_[rs][c4] = q;
    __syncthreads();
    if (rs == 0) {
        float4 A0 = rs_[0][c4], A1 = rs_[1][c4], A2 = rs_[2][c4], A3 = rs_[3][c4];
        float4 B0 = rq_[0][c4], B1 = rq_[1][c4], B2 = rq_[2][c4], B3 = rq_[3][c4];
        atomicAdd(&sums[c4 * 4 + 0], A0.x + A1.x + A2.x + A3.x);
        atomicAdd(&sums[c4 * 4 + 1], A0.y + A1.y + A2.y + A3.y);
        atomicAdd(&sums[c4 * 4 + 2], A0.z + A1.z + A2.z + A3.z);
        atomicAdd(&sums[c4 * 4 + 3], A0.w + A1.w + A2.w + A3.w);
        atomicAdd(&sqs[c4 * 4 + 0], B0.x + B1.x + B2.x + B3.x);
        atomicAdd(&sqs[c4 * 4 + 1], B0.y + B1.y + B2.y + B3.y);
        atomicAdd(&sqs[c4 * 4 + 2], B0.z + B1.z + B2.z + B3.z);
        atomicAdd(&sqs[c4 * 4 + 3], B0.w + B1.w + B2.w + B3.w);
    }
}

__global__ void __launch_bounds__(128) bn_apply_exp(
    const float* __restrict__ X, const float* __restrict__ sums,
    const float* __restrict__ sqs, const float* __restrict__ g,
    const float* __restrict__ b)
{
    int row = blockIdx.x;
    int c0 = 2 * threadIdx.x;
    float2 x = *(const float2*)&X[(size_t)row * DD + c0];
    float m0 = sums[c0] * (1.0f / NN), m1 = sums[c0 + 1] * (1.0f / NN);
    float v0 = sqs[c0] * (1.0f / NN) - m0 * m0;
    float v1 = sqs[c0 + 1] * (1.0f / NN) - m1 * m1;
    float y0 = (x.x - m0) * rsqrtf(v0 + EPS) * g[c0] + b[c0];
    float y1 = (x.y - m1) * rsqrtf(v1 + EPS) * g[c0 + 1] + b[c0 + 1];
    *(float2*)&g_bn1[(size_t)row * DD + c0] = make_float2(y0, y1);
    uint32_t w[3];
    packA(y0, y1, w);
    size_t bo = ((size_t)(c0 >> 4) * NN + row) * 24 + ((c0 & 15) >> 1) * 3;
    g_bn1A[bo + 0] = w[0];
    g_bn1A[bo + 1] = w[1];
    g_bn1A[bo + 2] = w[2];
}

__global__ void __launch_bounds__(256) bn_apply(
    const float* __restrict__ X, const float* __restrict__ sums,
    const float* __restrict__ sqs, const float* __restrict__ g,
    const float* __restrict__ b, float* __restrict__ Y)
{
    int c = threadIdx.x;
    size_t idx = (size_t)blockIdx.x * DD + c;
    float m = sums[c] * (1.0f / NN);
    float v = sqs[c] * (1.0f / NN) - m * m;
    Y[idx] = (X[idx] - m) * rsqrtf(v + EPS) * g[c] + b[c];
}

// ================= launch =================
extern "C" void kernel_launch(void* const* d_in, const int* in_sizes, int n_in,
                              void* d_out, int out_size)
{
    const float* A  = (const float*)d_in[0];
    const float* h  = (const float*)d_in[1];
    const float* Wq = (const float*)d_in[2];
    const float* Wk = (const float*)d_in[3];
    const float* Wv = (const float*)d_in[4];
    const float* Wo = (const float*)d_in[5];
    const float* g1 = (const float*)d_in[6];
    const float* b1 = (const float*)d_in[7];
    const float* g2 = (const float*)d_in[8];
    const float* b2 = (const float*)d_in[9];
    const float* W1 = (const float*)d_in[10];
    const float* W2 = (const float*)d_in[11];
    float* out = (float*)d_out;

    char *phA, *pattnA, *pbn1A, *pmidA, *pWoB, *pW1B, *pW2B;
    float *pX1, *pBN1, *pX2, *pStats;
    cudaGetSymbolAddress((void**)&phA,   g_hA);
    cudaGetSymbolAddress((void**)&pattnA, g_attnA);
    cudaGetSymbolAddress((void**)&pbn1A, g_bn1A);
    cudaGetSymbolAddress((void**)&pmidA, g_midA);
    cudaGetSymbolAddress((void**)&pWoB,  g_WoB);
    cudaGetSymbolAddress((void**)&pW1B,  g_W1B);
    cudaGetSymbolAddress((void**)&pW2B,  g_W2B);
    cudaGetSymbolAddress((void**)&pX1,   g_x1);
    cudaGetSymbolAddress((void**)&pBN1,  g_bn1);
    cudaGetSymbolAddress((void**)&pX2,   g_x2);
    cudaGetSymbolAddress((void**)&pStats, g_stats);

    cudaFuncSetAttribute(qkv_gemm_ex, cudaFuncAttributeMaxDynamicSharedMemorySize, GEMM_SMEM);
    cudaFuncSetAttribute(gemm_ex,     cudaFuncAttributeMaxDynamicSharedMemorySize, GEMM_SMEM);

    prep<<<NN + 512 + 384, 256>>>(A, h, Wq, Wk, Wv, Wo, W1, W2);

    dim3 gQKV(DD / BN, NN / BM, 3);     // (4, 128, 3) = 1536
    dim3 g256(DD / BN, NN / BM);        // (4, 128) = 512
    dim3 g512(FFD / BN, NN / BM);       // (8, 128) = 1024

    qkv_gemm_ex<<<gQKV, 128, GEMM_SMEM>>>(phA, pStats);  // V epilogue: Vsum

    attn_sparse<<<NN, 256>>>();

    gemm_ex<<<g256, 128, GEMM_SMEM>>>(pattnA, pWoB, pX1, DD, DD, 3, h);   // launch #4 -> ncu

    bn_stats<<<256, 256>>>(pX1, pStats + 256, pStats + 512);
    bn_apply_exp<<<NN, 128>>>(pX1, pStats + 256, pStats + 512, g1, b1);

    gemm_ex<<<g512, 128, GEMM_SMEM>>>(pbn1A, pW1B, nullptr, DD, FFD, 2, nullptr);
    gemm_ex<<<g256, 128, GEMM_SMEM>>>(pmidA, pW2B, pX2, FFD, DD, 3, pBN1);

    bn_stats<<<256, 256>>>(pX2, pStats + 768, pStats + 1024);
    bn_apply<<<NN, 256>>>(pX2, pStats + 768, pStats + 1024, g2, b2, out);
}

// round 17
// speedup vs baseline: 1.6118x; 1.6118x over previous
#include <cuda_runtime.h>
#include <cuda_bf16.h>
#include <math.h>
#include <stdint.h>

#define NN 4096
#define DD 256
#define HH 8
#define HDIM 32
#define ROWCAP 256
#define EPS 1e-5f
#define FFD 512

// ---------------- static scratch ----------------
__device__ int   g_cols[NN * ROWCAP];
__device__ float g_avals[NN * ROWCAP];
__device__ int   g_nnz[NN];
__device__ float g_Q[NN * DD];
__device__ float g_K[NN * DD];
__device__ float g_V[NN * DD];
__device__ float g_x1[NN * DD];
__device__ float g_bn1[NN * DD];
__device__ float g_x2[NN * DD];
__device__ float g_stats[1280];

// expanded 3xBF16 operand buffers (uint32 = bf16x2), 24 words per (chunk,row)
__device__ __align__(16) uint32_t g_hA  [NN * (DD / 16) * 24];
__device__ __align__(16) uint32_t g_attnA[NN * (DD / 16) * 24];
__device__ __align__(16) uint32_t g_bn1A[NN * (DD / 16) * 24];
__device__ __align__(16) uint32_t g_midA[NN * (FFD / 16) * 24];
__device__ __align__(16) uint32_t g_WqB [DD * (DD / 16) * 24];
__device__ __align__(16) uint32_t g_WkB [DD * (DD / 16) * 24];
__device__ __align__(16) uint32_t g_WvB [DD * (DD / 16) * 24];
__device__ __align__(16) uint32_t g_WoB [DD * (DD / 16) * 24];
__device__ __align__(16) uint32_t g_W1B [FFD * (DD / 16) * 24];
__device__ __align__(16) uint32_t g_W2B [DD * (FFD / 16) * 24];

// ================= helpers =================
__device__ __forceinline__ uint32_t smem_u32(const void* p) {
    uint32_t a;
    asm("{ .reg .u64 t; cvta.to.shared.u64 t, %1; cvt.u32.u64 %0, t; }" : "=r"(a) : "l"(p));
    return a;
}
__device__ __forceinline__ void ldm4(uint32_t addr, uint32_t& r0, uint32_t& r1,
                                     uint32_t& r2, uint32_t& r3) {
    asm volatile("ldmatrix.sync.aligned.m8n8.x4.shared.b16 {%0,%1,%2,%3}, [%4];"
                 : "=r"(r0), "=r"(r1), "=r"(r2), "=r"(r3) : "r"(addr));
}
__device__ __forceinline__ void mma16816(float* c, uint32_t a0, uint32_t a1,
                                         uint32_t a2, uint32_t a3,
                                         uint32_t b0, uint32_t b1) {
    asm volatile(
        "mma.sync.aligned.m16n8k16.row.col.f32.bf16.bf16.f32 "
        "{%0,%1,%2,%3}, {%4,%5,%6,%7}, {%8,%9}, {%0,%1,%2,%3};"
        : "+f"(c[0]), "+f"(c[1]), "+f"(c[2]), "+f"(c[3])
        : "r"(a0), "r"(a1), "r"(a2), "r"(a3), "r"(b0), "r"(b1));
}
#define CP16(dst, src) asm volatile("cp.async.cg.shared.global [%0], [%1], 16;" :: "r"(dst), "l"(src))
#define CPCOMMIT()     asm volatile("cp.async.commit_group;" ::: "memory")
#define CPWAIT2()      asm volatile("cp.async.wait_group 2;" ::: "memory")

__device__ __forceinline__ void splitf(float x, uint32_t& h, uint32_t& l) {
    __nv_bfloat16 hb = __float2bfloat16_rn(x);
    float hf = __bfloat162float(hb);
    __nv_bfloat16 lb = __float2bfloat16_rn(x - hf);
    h = (uint32_t)__bfloat16_as_ushort(hb);
    l = (uint32_t)__bfloat16_as_ushort(lb);
}
// A per float: [hi, lo, hi];  B per float: [hi, hi, lo]
__device__ __forceinline__ void packA(float a, float b, uint32_t* w) {
    uint32_t ha, la, hb, lb;
    splitf(a, ha, la); splitf(b, hb, lb);
    w[0] = ha | (la << 16); w[1] = ha | (hb << 16); w[2] = lb | (hb << 16);
}
__device__ __forceinline__ void packB(float a, float b, uint32_t* w) {
    uint32_t ha, la, hb, lb;
    splitf(a, ha, la); splitf(b, hb, lb);
    w[0] = ha | (ha << 16); w[1] = la | (hb << 16); w[2] = hb | (lb << 16);
}

// ================= merged prep: csr + expandA + expandB + zero stats =========
__global__ void __launch_bounds__(256) prep(
    const float* __restrict__ A, const float* __restrict__ h,
    const float* __restrict__ Wq, const float* __restrict__ Wk,
    const float* __restrict__ Wv, const float* __restrict__ Wo,
    const float* __restrict__ W1, const float* __restrict__ W2)
{
    __shared__ int cnt;
    int bid = blockIdx.x;
    if (bid < NN) {
        int row = bid;
        if (threadIdx.x == 0) cnt = 0;
        __syncthreads();
        const float4* Ar = (const float4*)(A + (size_t)row * NN);
        for (int c4 = threadIdx.x; c4 < NN / 4; c4 += 256) {
            float4 a4 = Ar[c4];
            float vals[4] = {a4.x, a4.y, a4.z, a4.w};
#pragma unroll
            for (int j = 0; j < 4; j++) {
                if (vals[j] != 0.0f) {
                    int p = atomicAdd(&cnt, 1);
                    if (p < ROWCAP) {
                        g_cols[row * ROWCAP + p] = c4 * 4 + j;
                        g_avals[row * ROWCAP + p] = vals[j];
                    }
                }
            }
        }
        __syncthreads();
        if (threadIdx.x == 0) g_nnz[row] = (cnt < ROWCAP) ? cnt : ROWCAP;
    } else if (bid < NN + 512) {
        int eb = bid - NN;
        if (eb < 5) g_stats[eb * 256 + threadIdx.x] = 0.0f;
        int idx = eb * 256 + threadIdx.x;
        const int hpr = DD / 8;
        int row = idx / hpr, wi = idx - row * hpr;
        int chunk = wi >> 1, half = wi & 1;
        const float4* s4 = (const float4*)&h[(size_t)row * DD + chunk * 16 + half * 8];
        float4 v0 = s4[0], v1 = s4[1];
        float f[8] = {v0.x, v0.y, v0.z, v0.w, v1.x, v1.y, v1.z, v1.w};
        uint32_t w[12];
#pragma unroll
        for (int p = 0; p < 4; p++) packA(f[2 * p], f[2 * p + 1], w + 3 * p);
        uint32_t* d = g_hA + ((size_t)chunk * NN + row) * 24 + half * 12;
        *(uint4*)(d + 0) = make_uint4(w[0], w[1], w[2], w[3]);
        *(uint4*)(d + 4) = make_uint4(w[4], w[5], w[6], w[7]);
        *(uint4*)(d + 8) = make_uint4(w[8], w[9], w[10], w[11]);
    } else {
        int eb = bid - NN - 512;
        int which = eb >> 6;
        int bx = eb & 63;
        const float* src; uint32_t* dst; int rows, K;
        switch (which) {
            case 0: src = Wq; dst = g_WqB; rows = DD;  K = DD;  break;
            case 1: src = Wk; dst = g_WkB; rows = DD;  K = DD;  break;
            case 2: src = Wv; dst = g_WvB; rows = DD;  K = DD;  break;
            case 3: src = Wo; dst = g_WoB; rows = DD;  K = DD;  break;
            case 4: src = W1; dst = g_W1B; rows = FFD; K = DD;  break;
            default: src = W2; dst = g_W2B; rows = DD; K = FFD; break;
        }
        int idx = bx * 256 + threadIdx.x;
        int hpr = K / 8;
        if (idx >= rows * hpr) return;
        int row = idx / hpr, wi = idx - row * hpr;
        int chunk = wi >> 1, half = wi & 1;
        const float4* s4 = (const float4*)&src[(size_t)row * K + chunk * 16 + half * 8];
        float4 v0 = s4[0], v1 = s4[1];
        float f[8] = {v0.x, v0.y, v0.z, v0.w, v1.x, v1.y, v1.z, v1.w};
        uint32_t w[12];
#pragma unroll
        for (int p = 0; p < 4; p++) packB(f[2 * p], f[2 * p + 1], w + 3 * p);
        uint32_t* d = dst + ((size_t)chunk * rows + row) * 24 + half * 12;
        *(uint4*)(d + 0) = make_uint4(w[0], w[1], w[2], w[3]);
        *(uint4*)(d + 4) = make_uint4(w[4], w[5], w[6], w[7]);
        *(uint4*)(d + 8) = make_uint4(w[8], w[9], w[10], w[11]);
    }
}

// ================= pipelined bf16 GEMM, 64x64 tile, 128 threads ==============
// 4 stages + wait_group 2; commit EVERY iter (race-free tail accounting).
// mode 0: plain  1: permute+scale (+Vsum)  2: relu+pack  3: +residual (+BN stats)
#define BM 64
#define BN 64
#define STAGEB 14336
#define NSTG 4
#define GEMM_SMEM (NSTG * STAGEB)

__device__ __forceinline__ void gemm_ex_body(
    const char* __restrict__ Aex, const char* __restrict__ Bex,
    float* __restrict__ Y, int K, int Ncr,
    int mode, const float* __restrict__ res, float scale,
    float* __restrict__ sums, float* __restrict__ sqs)
{
    extern __shared__ __align__(16) char sm[];
    uint32_t smb = smem_u32(sm);

    int tid = threadIdx.x;
    int lane = tid & 31;
    int wid = tid >> 5;          // 0..3
    int wm = wid >> 1;           // 0..1 -> m offset *32
    int wn = wid & 1;            // 0..1 -> n offset *32
    int m0 = blockIdx.y * BM;
    int n0 = blockIdx.x * BN;

    const size_t aChunk = (size_t)NN * 96;
    const size_t bChunk = (size_t)Ncr * 96;

    size_t aSrc[3], bSrc[3];
    uint32_t aDst[3], bDst[3];
#pragma unroll
    for (int i = 0; i < 3; i++) {
        int l = tid + i * 128;
        int row = l / 6, part = l - row * 6;
        aSrc[i] = (size_t)(m0 + row) * 96 + part * 16;
        aDst[i] = (uint32_t)(row * 112 + part * 16);
        bSrc[i] = (size_t)(n0 + row) * 96 + part * 16;
        bDst[i] = (uint32_t)(7168 + row * 112 + part * 16);
    }

    int nit = K / 16;

    // prologue: stages 0..2
#pragma unroll
    for (int s = 0; s < 3; s++) {
        uint32_t sb = smb + s * STAGEB;
#pragma unroll
        for (int i = 0; i < 3; i++) {
            CP16(sb + aDst[i], Aex + (size_t)s * aChunk + aSrc[i]);
            CP16(sb + bDst[i], Bex + (size_t)s * bChunk + bSrc[i]);
        }
        CPCOMMIT();
    }

    int la = lane & 15;
    int kha = (lane >> 4) & 1;
    int rb = (lane & 7) + (((lane >> 4) & 1) << 3);
    int khb = (lane >> 3) & 1;
    uint32_t aRow[2];
#pragma unroll
    for (int mt = 0; mt < 2; mt++)
        aRow[mt] = (uint32_t)((wm * 32 + mt * 16 + la) * 112);
    uint32_t bRow[2];
#pragma unroll
    for (int nt = 0; nt < 2; nt++)
        bRow[nt] = (uint32_t)(7168 + (wn * 32 + nt * 16 + rb) * 112);

    float acc[2][4][4] = {};

    for (int it = 0; it < nit; it++) {
        CPWAIT2();
        __syncthreads();
        int nc3 = it + 3;
        if (nc3 < nit) {
            uint32_t sb = smb + (nc3 % NSTG) * STAGEB;
#pragma unroll
            for (int i = 0; i < 3; i++) {
                CP16(sb + aDst[i], Aex + (size_t)nc3 * aChunk + aSrc[i]);
                CP16(sb + bDst[i], Bex + (size_t)nc3 * bChunk + bSrc[i]);
            }
        }
        CPCOMMIT();   // ALWAYS commit — exact wait_group accounting
        uint32_t base = smb + (it % NSTG) * STAGEB;
#pragma unroll
        for (int ks = 0; ks < 3; ks++) {
            uint32_t koff = (uint32_t)(2 * ks) * 16;
            uint32_t a[2][4], b[2][4];
#pragma unroll
            for (int mt = 0; mt < 2; mt++)
                ldm4(base + aRow[mt] + koff + (uint32_t)kha * 16,
                     a[mt][0], a[mt][1], a[mt][2], a[mt][3]);
#pragma unroll
            for (int nt = 0; nt < 2; nt++)
                ldm4(base + bRow[nt] + koff + (uint32_t)khb * 16,
                     b[nt][0], b[nt][1], b[nt][2], b[nt][3]);
#pragma unroll
            for (int mt = 0; mt < 2; mt++) {
#pragma unroll
                for (int nt = 0; nt < 2; nt++) {
                    mma16816(acc[mt][nt * 2 + 0], a[mt][0], a[mt][1], a[mt][2], a[mt][3],
                             b[nt][0], b[nt][1]);
                    mma16816(acc[mt][nt * 2 + 1], a[mt][0], a[mt][1], a[mt][2], a[mt][3],
                             b[nt][2], b[nt][3]);
                }
            }
        }
    }

    // ---- epilogue
    int gid = lane >> 2, tig = lane & 3;
#pragma unroll
    for (int n8 = 0; n8 < 4; n8++) {
        int col = n0 + wn * 32 + n8 * 8 + 2 * tig;
        float s0 = 0.f, s1 = 0.f, q0 = 0.f, q1 = 0.f;
#pragma unroll
        for (int mt = 0; mt < 2; mt++) {
#pragma unroll
            for (int half = 0; half < 2; half++) {
                int m = m0 + wm * 32 + mt * 16 + gid + half * 8;
                size_t rowoff = (size_t)m * Ncr;
                float v0 = acc[mt][n8][half * 2 + 0];
                float v1 = acc[mt][n8][half * 2 + 1];
                if (mode == 1) {
                    int p0 = (col & 7) * HDIM + (col >> 3);
                    int p1 = ((col + 1) & 7) * HDIM + ((col + 1) >> 3);
                    Y[rowoff + p0] = v0 * scale;
                    Y[rowoff + p1] = v1 * scale;
                    s0 += v0; s1 += v1;
                } else if (mode == 2) {
                    float r0 = fmaxf(v0, 0.f), r1 = fmaxf(v1, 0.f);
                    uint32_t w[3];
                    packA(r0, r1, w);
                    size_t base2 = ((size_t)(col >> 4) * NN + m) * 24 + ((col & 15) >> 1) * 3;
                    g_midA[base2 + 0] = w[0];
                    g_midA[base2 + 1] = w[1];
                    g_midA[base2 + 2] = w[2];
                } else if (mode == 3) {
                    float2 r = *(const float2*)&res[rowoff + col];
                    float y0 = v0 + r.x, y1 = v1 + r.y;
                    *(float2*)&Y[rowoff + col] = make_float2(y0, y1);
                    s0 += y0; q0 += y0 * y0;
                    s1 += y1; q1 += y1 * y1;
                } else {
                    *(float2*)&Y[rowoff + col] = make_float2(v0, v1);
                }
            }
        }
        if (mode == 1 && sums != nullptr) {
#pragma unroll
            for (int off = 4; off < 32; off <<= 1) {
                s0 += __shfl_xor_sync(0xffffffffu, s0, off);
                s1 += __shfl_xor_sync(0xffffffffu, s1, off);
            }
            if (gid == 0) {
                int p0 = (col & 7) * HDIM + (col >> 3);
                int p1 = ((col + 1) & 7) * HDIM + ((col + 1) >> 3);
                atomicAdd(&sums[p0], s0);
                atomicAdd(&sums[p1], s1);
            }
        } else if (mode == 3 && sums != nullptr) {
#pragma unroll
            for (int off = 4; off < 32; off <<= 1) {
                s0 += __shfl_xor_sync(0xffffffffu, s0, off);
                s1 += __shfl_xor_sync(0xffffffffu, s1, off);
                q0 += __shfl_xor_sync(0xffffffffu, q0, off);
                q1 += __shfl_xor_sync(0xffffffffu, q1, off);
            }
            if (gid == 0) {
                atomicAdd(&sums[col], s0);
                atomicAdd(&sums[col + 1], s1);
                atomicAdd(&sqs[col], q0);
                atomicAdd(&sqs[col + 1], q1);
            }
        }
    }
}

__global__ void __launch_bounds__(128) qkv_gemm_ex(const char* __restrict__ Aex,
                                                   float* __restrict__ stats) {
    int z = blockIdx.z;
    const char* Bex = (z == 0) ? (const char*)g_WqB : ((z == 1) ? (const char*)g_WkB : (const char*)g_WvB);
    float* Y = (z == 0) ? g_Q : ((z == 1) ? g_K : g_V);
    float scale = (z == 0) ? 0.0625f : 1.0f;
    gemm_ex_body(Aex, Bex, Y, DD, DD, 1, nullptr, scale,
                 (z == 2) ? stats : nullptr, nullptr);
}

__global__ void __launch_bounds__(128) gemm_ex(
    const char* __restrict__ Aex, const char* __restrict__ Bex,
    float* __restrict__ Y, int K, int Ncr, int mode, const float* __restrict__ res,
    float* __restrict__ sums, float* __restrict__ sqs)
{
    gemm_ex_body(Aex, Bex, Y, K, Ncr, mode, res, 1.0f, sums, sqs);
}

// ================= attention (R11-proven) ==================
__global__ void __launch_bounds__(256) attn_sparse() {
    __shared__ float s_part[8][DD];
    __shared__ float s_zp[8][HH];
    __shared__ float sm_attn[DD];
    __shared__ int   s_cols[ROWCAP];
    __shared__ float s_av[ROWCAP];
    int n = blockIdx.x;
    int tid = threadIdx.x;
    int w = tid >> 5;
    int lane = tid & 31;
    int d0 = lane * 8;

    int nnz = g_nnz[n];
    if (tid < nnz) {
        s_cols[tid] = g_cols[(size_t)n * ROWCAP + tid];
        s_av[tid]   = g_avals[(size_t)n * ROWCAP + tid];
    }
    float4 q0 = *(const float4*)&g_Q[(size_t)n * DD + d0];
    float4 q1 = *(const float4*)&g_Q[(size_t)n * DD + d0 + 4];
    __syncthreads();

    float a0 = 0.f, a1 = 0.f, a2 = 0.f, a3 = 0.f;
    float a4 = 0.f, a5 = 0.f, a6 = 0.f, a7 = 0.f;
    float zloc = 0.0f;

    int i = w;
    for (; i + 8 < nnz; i += 16) {
        int mA = s_cols[i],   mB = s_cols[i + 8];
        float avA = s_av[i],  avB = s_av[i + 8];
        const float* KrA = &g_K[(size_t)mA * DD + d0];
        const float* VrA = &g_V[(size_t)mA * DD + d0];
        const float* KrB = &g_K[(size_t)mB * DD + d0];
        const float* VrB = &g_V[(size_t)mB * DD + d0];
        float4 kA0 = *(const float4*)&KrA[0];
        float4 kA1 = *(const float4*)&KrA[4];
        float4 kB0 = *(const float4*)&KrB[0];
        float4 kB1 = *(const float4*)&KrB[4];
        float4 vA0 = *(const float4*)&VrA[0];
        float4 vA1 = *(const float4*)&VrA[4];
        float4 vB0 = *(const float4*)&VrB[0];
        float4 vB1 = *(const float4*)&VrB[4];
        float sA = q0.x * kA0.x + q0.y * kA0.y + q0.z * kA0.z + q0.w * kA0.w
                 + q1.x * kA1.x + q1.y * kA1.y + q1.z * kA1.z + q1.w * kA1.w;
        float sB = q0.x * kB0.x + q0.y * kB0.y + q0.z * kB0.z + q0.w * kB0.w
                 + q1.x * kB1.x + q1.y * kB1.y + q1.z * kB1.z + q1.w * kB1.w;
        sA += __shfl_xor_sync(0xffffffffu, sA, 1);
        sB += __shfl_xor_sync(0xffffffffu, sB, 1);
        sA += __shfl_xor_sync(0xffffffffu, sA, 2);
        sB += __shfl_xor_sync(0xffffffffu, sB, 2);
        float eA = __expf(avA * sA);
        float eB = __expf(avB * sB);
        float emA = eA - 1.0f, emB = eB - 1.0f;
        a0 += emA * vA0.x + emB * vB0.x;
        a1 += emA * vA0.y + emB * vB0.y;
        a2 += emA * vA0.z + emB * vB0.z;
        a3 += emA * vA0.w + emB * vB0.w;
        a4 += emA * vA1.x + emB * vB1.x;
        a5 += emA * vA1.y + emB * vB1.y;
        a6 += emA * vA1.z + emB * vB1.z;
        a7 += emA * vA1.w + emB * vB1.w;
        if ((lane & 3) == 0) zloc += eA + eB;
    }
    if (i < nnz) {
        int m = s_cols[i];
        float av_i = s_av[i];
        const float* Kr = &g_K[(size_t)m * DD + d0];
        const float* Vr = &g_V[(size_t)m * DD + d0];
        float4 k0 = *(const float4*)&Kr[0];
        float4 k1 = *(const float4*)&Kr[4];
        float4 v0 = *(const float4*)&Vr[0];
        float4 v1 = *(const float4*)&Vr[4];
        float s = q0.x * k0.x + q0.y * k0.y + q0.z * k0.z + q0.w * k0.w
                + q1.x * k1.x + q1.y * k1.y + q1.z * k1.z + q1.w * k1.w;
        s += __shfl_xor_sync(0xffffffffu, s, 1);
        s += __shfl_xor_sync(0xffffffffu, s, 2);
        float e = __expf(av_i * s);
        float em1 = e - 1.0f;
        a0 += em1 * v0.x; a1 += em1 * v0.y; a2 += em1 * v0.z; a3 += em1 * v0.w;
        a4 += em1 * v1.x; a5 += em1 * v1.y; a6 += em1 * v1.z; a7 += em1 * v1.w;
        if ((lane & 3) == 0) zloc += e;
    }

    *(float4*)&s_part[w][d0]     = make_float4(a0, a1, a2, a3);
    *(float4*)&s_part[w][d0 + 4] = make_float4(a4, a5, a6, a7);
    if ((lane & 3) == 0) s_zp[w][lane >> 2] = zloc;
    __syncthreads();

    {
        int c = tid;
        int p = (c & 7) * HDIM + (c >> 3);
        float acc = g_stats[p];
        float z = (float)(NN - nnz);
#pragma unroll
        for (int ww = 0; ww < 8; ww++) {
            acc += s_part[ww][p];
            z += s_zp[ww][c & 7];
        }
        sm_attn[c] = acc / z;
    }
    __syncthreads();
    if (tid < 128) {
        int c0 = 2 * tid;
        float v0 = sm_attn[c0], v1 = sm_attn[c0 + 1];
        uint32_t ww[3];
        packA(v0, v1, ww);
        size_t b = ((size_t)(c0 >> 4) * NN + n) * 24 + ((c0 & 15) >> 1) * 3;
        g_attnA[b + 0] = ww[0];
        g_attnA[b + 1] = ww[1];
        g_attnA[b + 2] = ww[2];
    }
}

// ================= batchnorm apply =================
__global__ void __launch_bounds__(128) bn_apply_exp(
    const float* __restrict__ X, const float* __restrict__ sums,
    const float* __restrict__ sqs, const float* __restrict__ g,
    const float* __restrict__ b)
{
    int row = blockIdx.x;
    int c0 = 2 * threadIdx.x;
    float2 x = *(const float2*)&X[(size_t)row * DD + c0];
    float m0 = sums[c0] * (1.0f / NN), m1 = sums[c0 + 1] * (1.0f / NN);
    float v0 = sqs[c0] * (1.0f / NN) - m0 * m0;
    float v1 = sqs[c0 + 1] * (1.0f / NN) - m1 * m1;
    float y0 = (x.x - m0) * rsqrtf(v0 + EPS) * g[c0] + b[c0];
    float y1 = (x.y - m1) * rsqrtf(v1 + EPS) * g[c0 + 1] + b[c0 + 1];
    *(float2*)&g_bn1[(size_t)row * DD + c0] = make_float2(y0, y1);
    uint32_t w[3];
    packA(y0, y1, w);
    size_t bo = ((size_t)(c0 >> 4) * NN + row) * 24 + ((c0 & 15) >> 1) * 3;
    g_bn1A[bo + 0] = w[0];
    g_bn1A[bo + 1] = w[1];
    g_bn1A[bo + 2] = w[2];
}

__global__ void __launch_bounds__(256) bn_apply(
    const float* __restrict__ X, const float* __restrict__ sums,
    const float* __restrict__ sqs, const float* __restrict__ g,
    const float* __restrict__ b, float* __restrict__ Y)
{
    int c = threadIdx.x;
    size_t idx = (size_t)blockIdx.x * DD + c;
    float m = sums[c] * (1.0f / NN);
    float v = sqs[c] * (1.0f / NN) - m * m;
    Y[idx] = (X[idx] - m) * rsqrtf(v + EPS) * g[c] + b[c];
}

// ================= launch =================
extern "C" void kernel_launch(void* const* d_in, const int* in_sizes, int n_in,
                              void* d_out, int out_size)
{
    const float* A  = (const float*)d_in[0];
    const float* h  = (const float*)d_in[1];
    const float* Wq = (const float*)d_in[2];
    const float* Wk = (const float*)d_in[3];
    const float* Wv = (const float*)d_in[4];
    const float* Wo = (const float*)d_in[5];
    const float* g1 = (const float*)d_in[6];
    const float* b1 = (const float*)d_in[7];
    const float* g2 = (const float*)d_in[8];
    const float* b2 = (const float*)d_in[9];
    const float* W1 = (const float*)d_in[10];
    const float* W2 = (const float*)d_in[11];
    float* out = (float*)d_out;

    char *phA, *pattnA, *pbn1A, *pmidA, *pWoB, *pW1B, *pW2B;
    float *pX1, *pBN1, *pX2, *pStats;
    cudaGetSymbolAddress((void**)&phA,   g_hA);
    cudaGetSymbolAddress((void**)&pattnA, g_attnA);
    cudaGetSymbolAddress((void**)&pbn1A, g_bn1A);
    cudaGetSymbolAddress((void**)&pmidA, g_midA);
    cudaGetSymbolAddress((void**)&pWoB,  g_WoB);
    cudaGetSymbolAddress((void**)&pW1B,  g_W1B);
    cudaGetSymbolAddress((void**)&pW2B,  g_W2B);
    cudaGetSymbolAddress((void**)&pX1,   g_x1);
    cudaGetSymbolAddress((void**)&pBN1,  g_bn1);
    cudaGetSymbolAddress((void**)&pX2,   g_x2);
    cudaGetSymbolAddress((void**)&pStats, g_stats);

    cudaFuncSetAttribute(qkv_gemm_ex, cudaFuncAttributeMaxDynamicSharedMemorySize, GEMM_SMEM);
    cudaFuncSetAttribute(gemm_ex,     cudaFuncAttributeMaxDynamicSharedMemorySize, GEMM_SMEM);

    prep<<<NN + 512 + 384, 256>>>(A, h, Wq, Wk, Wv, Wo, W1, W2);

    dim3 gQKV(DD / BN, NN / BM, 3);     // (4, 64, 3) = 768
    dim3 g256(DD / BN, NN / BM);        // (4, 64) = 256
    dim3 g512(FFD / BN, NN / BM);       // (8, 64) = 512

    qkv_gemm_ex<<<gQKV, 128, GEMM_SMEM>>>(phA, pStats);   // V epilogue: Vsum

    attn_sparse<<<NN, 256>>>();

    // Wo proj + residual + fused BN1 stats
    gemm_ex<<<g256, 128, GEMM_SMEM>>>(pattnA, pWoB, pX1, DD, DD, 3, h,
                                      pStats + 256, pStats + 512);

    bn_apply_exp<<<NN, 128>>>(pX1, pStats + 256, pStats + 512, g1, b1);

    gemm_ex<<<g512, 128, GEMM_SMEM>>>(pbn1A, pW1B, nullptr, DD, FFD, 2, nullptr,
                                      nullptr, nullptr);
    // W2 + residual + fused BN2 stats
    gemm_ex<<<g256, 128, GEMM_SMEM>>>(pmidA, pW2B, pX2, FFD, DD, 3, pBN1,
                                      pStats + 768, pStats + 1024);

    bn_apply<<<NN, 256>>>(pX2, pStats + 768, pStats + 1024, g2, b2, out);
}